// round 3
// baseline (speedup 1.0000x reference)
#include <cuda_runtime.h>
#include <math.h>

#define BMAX 16
#define TMAX 64

__constant__ float c_anchx[9] = {10.f,16.f,33.f,30.f,62.f,59.f,116.f,156.f,373.f};
__constant__ float c_anchy[9] = {13.f,30.f,23.f,61.f,45.f,119.f,90.f,198.f,326.f};
// manch per layer (= ANCHORS[group*3+a]/stride), layer order group={2,1,0}, stride={32,16,8}
__constant__ float c_manch[3][6] = {
    {3.625f, 2.8125f, 4.875f, 6.1875f, 11.65625f, 10.1875f},
    {1.875f, 3.8125f, 3.875f, 2.8125f, 3.6875f,   7.4375f},
    {1.25f,  1.625f,  2.0f,   3.75f,   4.125f,    2.875f }
};
__constant__ float c_stride[3] = {32.f, 16.f, 8.f};

__device__ double   g_acc   = 0.0;
__device__ unsigned g_count = 0u;

__device__ __forceinline__ float slog(float x) { return x > 0.f ? __logf(x) : -100.f; }
__device__ __forceinline__ float sigm(float x) { return 1.f/(1.f + __expf(-x)); }

// Single fused kernel. blockIdx.x partitions cells across the 3 layers,
// blockIdx.y = batch. Each block recomputes its (layer,batch) targets into
// shared memory (targets are tiny and L2-resident), then runs the per-cell
// loss, block-reduces, and the globally-last block writes the output.
__global__ __launch_bounds__(256)
void k_loss(const float* __restrict__ r0, const float* __restrict__ r1,
            const float* __restrict__ r2, const float* __restrict__ tg,
            int T,
            int HW0, int W0, int HW1, int W1, int HW2, int W2,
            int nb0, int nb01, float* __restrict__ out)
{
    __shared__ float4 sbox[TMAX];     // target tl.x, tl.y, br.x, br.y
    __shared__ float2 smeta[TMAX];    // 0.7*area_b, key-as-int-bits
    __shared__ float4 sext4[TMAX];    // fx, fy, log(w/aw), log(h/ah)
    __shared__ float2 sext2[TMAX];    // scale, cls-as-int-bits
    __shared__ int   s_w0, scnt;
    __shared__ float swsum[8];

    int bx = blockIdx.x;
    int layer; const float* raw; int HW, W, base;
    if (bx < nb0)       { layer = 0; raw = r0; HW = HW0; W = W0; base = 0;    }
    else if (bx < nb01) { layer = 1; raw = r1; HW = HW1; W = W1; base = nb0;  }
    else                { layer = 2; raw = r2; HW = HW2; W = W2; base = nb01; }

    int b   = blockIdx.y;
    int tid = threadIdx.x;
    int fs  = W;
    float fsf = (float)fs;
    float stride = c_stride[layer];
    int group = 2 - layer;

    // ---- Phase 1: target preprocessing into shared (threads 0..63) ----
    bool valid = false;
    int pre = 0;
    float cf = 0.f, tx = 0.f, ty = 0.f, tw = 0.f, th = 0.f;
    unsigned ball = 0;
    if (tid < 64) {
        if (tid < T) {
            const float* L = tg + ((size_t)b*T + tid)*5;
            cf = L[0];
            float x = L[1], y = L[2], w = L[3], h = L[4];
            valid = (cf + x + y + w + h) > 0.f;
            tx = x*fsf; ty = y*fsf; tw = w*fsf; th = h*fsf;
        }
        ball = __ballot_sync(0xffffffffu, valid);
        int lane = tid & 31;
        pre = __popc(ball & ((1u << lane) - 1u));
        if (tid == 0) s_w0 = __popc(ball);
    }
    __syncthreads();
    if (tid < 64) {
        if (tid >= 32) pre += s_w0;
        if (tid == 63) scnt = s_w0 + __popc(ball);
        if (valid) {
            float twth = tw*th;
            // argmax over 9 anchor IoUs (first max wins, matching jnp.argmax)
            float best = -1.f; int bi = 0;
            #pragma unroll
            for (int i = 0; i < 9; ++i) {
                float aw = c_anchx[i]/stride, ah = c_anchy[i]/stride;
                float mw = fminf(tw, aw), mh = fminf(th, ah);
                float inter = (mw > 0.f && mh > 0.f) ? mw*mh : 0.f;
                float iou = inter / (twth + aw*ah - inter);
                if (iou > best) { best = iou; bi = i; }
            }
            int bn = bi - (bi/3)*3;
            bool sel = (bi/3) == group;

            sbox[pre] = make_float4(tx - 0.5f*tw, ty - 0.5f*th,
                                    tx + 0.5f*tw, ty + 0.5f*th);
            int key = -1;
            if (sel) {
                int gi = (int)tx, gj = (int)ty;
                if (gi >= 0 && gi < fs && gj >= 0 && gj < fs) {  // mode='drop'
                    key = (bn << 28) | (gj << 14) | gi;
                    float aw = c_manch[layer][2*bn];
                    float ah = c_manch[layer][2*bn + 1];
                    sext4[pre] = make_float4(tx - (float)gi, ty - (float)gj,
                                             logf(tw/aw + 1e-16f),
                                             logf(th/ah + 1e-16f));
                    sext2[pre] = make_float2(sqrtf(2.f - twth/(fsf*fsf)),
                                             __int_as_float((int)cf));
                }
            }
            smeta[pre] = make_float2(0.7f*twth, __int_as_float(key));
        }
    }
    __syncthreads();

    // ---- Phase 2: per-cell loss ----
    int cell = (bx - base)*256 + tid;
    float lsum = 0.f;
    if (cell < 3*HW) {
        int a  = cell / HW;
        int hw = cell - a*HW;
        int h  = hw / W;
        int w  = hw - h*W;
        const float* p = raw + ((size_t)b*255 + (size_t)a*85)*(size_t)HW + hw;
        float o0 = __ldg(p);
        float o1 = __ldg(p + HW);
        float o2 = __ldg(p + 2*HW);
        float o3 = __ldg(p + 3*HW);
        float o4 = __ldg(p + 4*HW);
        float s0 = sigm(o0), s1 = sigm(o1), s4 = sigm(o4);
        float maw = c_manch[layer][2*a];
        float mah = c_manch[layer][2*a + 1];
        float pw = __expf(o2)*maw, ph = __expf(o3)*mah;
        float px = s0 + (float)w, py = s1 + (float)h;
        float atlx = px - 0.5f*pw, atly = py - 0.5f*ph;
        float abrx = px + 0.5f*pw, abry = py + 0.5f*ph;
        float ca = 0.7f*(pw*ph);
        int ckey = (a << 28) | (h << 14) | w;

        bool any = false;
        int tmi = -1;
        int cnt = scnt;
        for (int t = 0; t < cnt; ++t) {
            float4 bb = sbox[t];
            float2 mm = smeta[t];
            float ix = fminf(abrx, bb.z) - fmaxf(atlx, bb.x);
            float iy = fminf(abry, bb.w) - fmaxf(atly, bb.y);
            float ai = ix*iy;
            // piou > 0.7  <=>  ix>0 & iy>0 & 1.7*ai > 0.7*(area_a+area_b)
            if (ix > 0.f && iy > 0.f && 1.7f*ai > ca + mm.x) any = true;
            if (__float_as_int(mm.y) == ckey) tmi = t;   // last match wins
        }

        if (tmi >= 0) {
            float4 e4 = sext4[tmi];
            float2 e2 = sext2[tmi];
            float fx = e4.x, fy = e4.y, tlw = e4.z, tlh = e4.w, sc = e2.x;
            int cls = __float_as_int(e2.y);
            float ts2 = sc*sc;
            // BCE(xy) weighted by scale^2
            lsum -= ts2*( fx*slog(s0) + (1.f - fx)*slog(1.f - s0)
                        + fy*slog(s1) + (1.f - fy)*slog(1.f - s1) );
            // 0.5 * scale^2 * (wh diff)^2
            float dw = o2 - tlw, dh = o3 - tlh;
            lsum += 0.5f*ts2*(dw*dw + dh*dh);
            // obj BCE with target 1
            lsum -= slog(s4);
            // class BCE over 80 channels (only at assigned cells)
            for (int c = 0; c < 80; ++c) {
                float oc = __ldg(p + (size_t)(5 + c)*HW);
                float scc = sigm(oc);
                lsum -= (c == cls) ? slog(scc) : slog(1.f - scc);
            }
        } else if (!any) {
            // obj BCE with target 0 where obj_mask = 1
            lsum -= slog(1.f - s4);
        }
        // (any && tmi<0) -> obj_mask = 0 -> zero contribution
    }

    // ---- Phase 3: block reduction + single atomic per block ----
    #pragma unroll
    for (int off = 16; off; off >>= 1)
        lsum += __shfl_xor_sync(0xffffffffu, lsum, off);
    if ((tid & 31) == 0) swsum[tid >> 5] = lsum;
    __syncthreads();
    if (tid == 0) {
        double bsum = 0.0;
        #pragma unroll
        for (int i = 0; i < 8; ++i) bsum += (double)swsum[i];
        atomicAdd(&g_acc, bsum);
        __threadfence();
        unsigned total = gridDim.x * gridDim.y;
        unsigned prev = atomicAdd(&g_count, 1u);
        if (prev == total - 1u) {
            out[0] = (float)g_acc;
            g_acc = 0.0;        // reset for next graph replay
            g_count = 0u;
        }
    }
}

extern "C" void kernel_launch(void* const* d_in, const int* in_sizes, int n_in,
                              void* d_out, int out_size)
{
    const float* r0 = (const float*)d_in[0];
    const float* r1 = (const float*)d_in[1];
    const float* r2 = (const float*)d_in[2];
    const float* targets = (const float*)d_in[3];
    const int B = 16;
    int T = in_sizes[3] / (B*5);
    if (T > TMAX) T = TMAX;

    int HW0 = in_sizes[0] / (B*255);
    int HW1 = in_sizes[1] / (B*255);
    int HW2 = in_sizes[2] / (B*255);
    int W0 = (int)(sqrt((double)HW0) + 0.5);
    int W1 = (int)(sqrt((double)HW1) + 0.5);
    int W2 = (int)(sqrt((double)HW2) + 0.5);

    int nb0 = (3*HW0 + 255)/256;
    int nb1 = (3*HW1 + 255)/256;
    int nb2 = (3*HW2 + 255)/256;
    dim3 lgrid(nb0 + nb1 + nb2, B);
    k_loss<<<lgrid, 256>>>(r0, r1, r2, targets, T,
                           HW0, W0, HW1, W1, HW2, W2,
                           nb0, nb0 + nb1, (float*)d_out);
}